// round 15
// baseline (speedup 1.0000x reference)
#include <cuda_runtime.h>
#include <cuda_fp16.h>
#include <cstdint>
#include <math.h>

#define BSZ 4
#define NN 4096
#define FD 256
#define KC 128
#define NCH (NN / KC)
#define ZSPLIT 32
#define LOG2E 1.4426950408889634f

// ---------------- scratch ----------------
__device__ __half g_hnT[BSZ * FD * NN];      // [b][f][j] = h[j,f]/S_j, fp16
__device__ float g_f1[BSZ * NN];
__device__ float g_f2[BSZ * NN];
__device__ float g_c[BSZ * NN];              // lrelu(maxf1 + f2_j), log2 units
__device__ float g_Zp[ZSPLIT][BSZ * NN];
__device__ uint32_t g_adjp[BSZ * NN * (NN / 32)];  // packed adj bits, 8MB

// ---------------- helpers ----------------
__device__ __forceinline__ uint32_t smem_u32(const void* p) {
    uint32_t a;
    asm("{ .reg .u64 t; cvta.to.shared.u64 t, %1; cvt.u32.u64 %0, t; }" : "=r"(a) : "l"(p));
    return a;
}
__device__ __forceinline__ float tf32r(float x) {
    uint32_t r;
    asm("cvt.rna.tf32.f32 %0, %1;" : "=r"(r) : "f"(x));
    return __uint_as_float(r);
}
__device__ __forceinline__ float ex2(float y) {   // MUFU exp2
    float r;
    asm("ex2.approx.ftz.f32 %0, %1;" : "=f"(r) : "f"(y));
    return r;
}
__device__ __forceinline__ void cp16(uint32_t dst, const void* src) {
    asm volatile("cp.async.cg.shared.global [%0], [%1], 16;" :: "r"(dst), "l"(src));
}
#define CP_COMMIT() asm volatile("cp.async.commit_group;" ::: "memory")
#define CP_WAIT0()  asm volatile("cp.async.wait_group 0;" ::: "memory")

__device__ __forceinline__ float fexp2(float y) {  // FMA-pipe 2^y (epilogue)
    float yr = y + 12582912.0f;
    int n = __float_as_int(yr) - 0x4B400000;
    float r = y - (yr - 12582912.0f);
    float p = fmaf(0.0013333558f, r, 0.0096181291f);
    p = fmaf(p, r, 0.0555041086f);
    p = fmaf(p, r, 0.2402265069f);
    p = fmaf(p, r, 0.6931471806f);
    p = fmaf(p, r, 1.0f);
    return __int_as_float(__float_as_int(p) + (n << 23));
}
__device__ __forceinline__ float felu(float x) {
    float q = fmaf(0.0083333338f, x, 0.0416666679f);
    q = fmaf(q, x, 0.16666667f);
    q = fmaf(q, x, 0.5f);
    q = fmaf(q, x, 1.0f);
    float small = x * q;
    float big = fexp2(x * LOG2E) - 1.0f;
    float neg = (x >= -0.25f) ? small : big;
    return (x > 0.f) ? x : neg;
}
__device__ __forceinline__ void ldsm4(uint32_t* r, uint32_t addr) {
    asm volatile("ldmatrix.sync.aligned.m8n8.x4.shared.b16 {%0,%1,%2,%3}, [%4];"
                 : "=r"(r[0]), "=r"(r[1]), "=r"(r[2]), "=r"(r[3]) : "r"(addr));
}
__device__ __forceinline__ void mma_f16(float* d, const uint32_t* a, const uint32_t* b2) {
    asm volatile(
        "mma.sync.aligned.m16n8k16.row.col.f32.f16.f16.f32 "
        "{%0,%1,%2,%3}, {%4,%5,%6,%7}, {%8,%9}, {%0,%1,%2,%3};"
        : "+f"(d[0]), "+f"(d[1]), "+f"(d[2]), "+f"(d[3])
        : "r"(a[0]), "r"(a[1]), "r"(a[2]), "r"(a[3]), "r"(b2[0]), "r"(b2[1]));
}
__device__ __forceinline__ void mma_tf32(float* d, const uint32_t* a, const uint32_t* bb) {
    asm volatile(
        "mma.sync.aligned.m16n8k8.row.col.f32.tf32.tf32.f32 "
        "{%0,%1,%2,%3}, {%4,%5,%6,%7}, {%8,%9}, {%0,%1,%2,%3};"
        : "+f"(d[0]), "+f"(d[1]), "+f"(d[2]), "+f"(d[3])
        : "r"(a[0]), "r"(a[1]), "r"(a[2]), "r"(a[3]), "r"(bb[0]), "r"(bb[1]));
}

// ---------------------------------------------------------------------------
// L1: fused  v = (W@a)*log2e  +  f1 = X.v1, f2 = X.v2
// ---------------------------------------------------------------------------
__global__ __launch_bounds__(512) void k_f12v(const float* __restrict__ X,
                                              const float* __restrict__ W,
                                              const float* __restrict__ a) {
    __shared__ float sa[2 * FD];
    __shared__ float sv[2 * FD];
    const int t = threadIdx.x, lane = t & 31, w = t >> 5;
    sa[t] = a[t];
    __syncthreads();
    if (t < FD) {
        float s1 = 0.f, s2 = 0.f;
        const float* wr = W + (size_t)t * FD;
#pragma unroll 4
        for (int f = 0; f < FD; f++) {
            float wv = wr[f];
            s1 = fmaf(wv, sa[f], s1);
            s2 = fmaf(wv, sa[FD + f], s2);
        }
        sv[t] = s1 * LOG2E;
        sv[FD + t] = s2 * LOG2E;
    }
    __syncthreads();
    const int R0 = blockIdx.x * 64;
#pragma unroll
    for (int rr = 0; rr < 4; rr++) {
        const int row = R0 + w * 4 + rr;
        const float* xr = X + (size_t)row * FD;
        float s1 = 0.f, s2 = 0.f;
#pragma unroll
        for (int k = lane; k < FD; k += 32) {
            float xv = xr[k];
            s1 = fmaf(xv, sv[k], s1);
            s2 = fmaf(xv, sv[FD + k], s2);
        }
#pragma unroll
        for (int o = 16; o; o >>= 1) {
            s1 += __shfl_xor_sync(~0u, s1, o);
            s2 += __shfl_xor_sync(~0u, s2, o);
        }
        if (lane == 0) { g_f1[row] = s1; g_f2[row] = s2; }
    }
}

// ---------------------------------------------------------------------------
// L2a: c_j = lrelu(maxf1 + f2_j)  (one block per batch; hoisted out of k_Zc)
// ---------------------------------------------------------------------------
__global__ __launch_bounds__(256) void k_cmax() {
    __shared__ float red[256];
    const int b = blockIdx.x;
    const int tid = threadIdx.x;
    float m = -1e30f;
    for (int i = tid; i < NN; i += 256)
        m = fmaxf(m, g_f1[b * NN + i]);
    red[tid] = m;
    __syncthreads();
#pragma unroll
    for (int o = 128; o; o >>= 1) {
        if (tid < o) red[tid] = fmaxf(red[tid], red[tid + o]);
        __syncthreads();
    }
    const float mf = red[0];
    for (int j = tid; j < NN; j += 256) {
        float s = mf + g_f2[b * NN + j];
        g_c[b * NN + j] = fmaxf(s, 0.2f * s);
    }
}

// ---------------------------------------------------------------------------
// L2b: shifted partial sums + adj bit-packing (split-range half)
//   grid (NN/128, ZSPLIT/2, BSZ), 128 threads. Reads g_c (no reduction).
// ---------------------------------------------------------------------------
__global__ __launch_bounds__(128) void k_Zc(const int* __restrict__ adj, int split0) {
    const int b = blockIdx.z;
    const int tid = threadIdx.x;
    const int j = blockIdx.x * 128 + tid;
    const int split = split0 + blockIdx.y;
    const int ilen = NN / ZSPLIT;
    const int i0 = split * ilen;
    const int wq = blockIdx.x * 4 + (tid >> 5);
    const int wl = tid & 31;

    const float f2j = g_f2[b * NN + j];
    const float cj = g_c[b * NN + j];

    const int* ap = adj + ((size_t)b * NN + i0) * NN + j;
    const float* f1p = g_f1 + b * NN + i0;
    uint32_t* pk = g_adjp + (size_t)(b * NN + i0) * (NN / 32) + wq;
    float acc = 0.f;
#pragma unroll 8
    for (int i = 0; i < ilen; i++) {
        int mm = ap[(size_t)i * NN];
        uint32_t blt = __ballot_sync(~0u, mm > 0);
        if (wl == 0) pk[(size_t)i * (NN / 32)] = blt;
        float y = f1p[i] + f2j;
        y = fmaxf(y, 0.2f * y) - cj;
        float e = ex2(y);
        acc += (mm > 0) ? e : 0.f;
    }
    g_Zp[split][b * NN + j] = acc;
}

// ---------------------------------------------------------------------------
// L3: hnT[b][f][j] = fp16( (X@W)[j,f] / S_j )  via tf32 mma + smem transpose
// ---------------------------------------------------------------------------
#define HG_ZI 0
#define HG_A 64
#define HG_ASTG (32 * 72)
#define HG_B (64 + 2 * HG_ASTG)
#define HG_BSTG (32 * 264)
#define HG_FLOATS (HG_B + 2 * HG_BSTG)
__global__ void __launch_bounds__(256, 2) k_hgen(const float* __restrict__ X,
                                                 const float* __restrict__ W) {
    extern __shared__ float sm[];
    const uint32_t smb = smem_u32(sm);
    const int t = threadIdx.x, lane = t & 31, wn = t >> 5, g = lane >> 2;
    const int R0 = blockIdx.x * 64;
    const int ia = t & 63, kh = (t >> 6) * 8;
    const int kb = t >> 3, seg = t & 7;

    if (t < 64) {
        float z = 0.f;
#pragma unroll
        for (int s = 0; s < ZSPLIT; s++) z += g_Zp[s][R0 + t];
        sm[HG_ZI + t] = 1.0f / z;
    }

    const float* xrow = X + (size_t)(R0 + ia) * FD + kh;
    {
        const float* src = W + (size_t)kb * FD + seg * 4;
        uint32_t dst = smb + (HG_B + kb * 264 + seg * 4) * 4;
#pragma unroll
        for (int q = 0; q < 8; q++) cp16(dst + q * 128, src + q * 32);
        CP_COMMIT();
    }

    float acc[4][4][4] = {};
    for (int c = 0; c < 8; c++) {
        const int aoff = HG_A + (c & 1) * HG_ASTG;
        const int boff = HG_B + (c & 1) * HG_BSTG;
        float4 x0 = *(const float4*)(xrow + c * 32);
        float4 x1 = *(const float4*)(xrow + c * 32 + 4);
        float e[8] = {x0.x, x0.y, x0.z, x0.w, x1.x, x1.y, x1.z, x1.w};
#pragma unroll
        for (int q = 0; q < 8; q++)
            sm[aoff + (kh + q) * 72 + ia] = tf32r(e[q]);
        CP_WAIT0();
        __syncthreads();
        if (c < 7) {
            const float* src = W + (size_t)((c + 1) * 32 + kb) * FD + seg * 4;
            uint32_t dst = smb + (HG_B + ((c + 1) & 1) * HG_BSTG + kb * 264 + seg * 4) * 4;
#pragma unroll
            for (int q = 0; q < 8; q++) cp16(dst + q * 128, src + q * 32);
            CP_COMMIT();
        }
        const uint32_t* smu = (const uint32_t*)sm;
#pragma unroll
        for (int kf = 0; kf < 4; kf++) {
            const int krow = kf * 8 + (lane & 3);
            uint32_t a[4][4];
#pragma unroll
            for (int mf = 0; mf < 4; mf++) {
                int base = aoff + krow * 72 + mf * 16 + g;
                a[mf][0] = smu[base];
                a[mf][1] = smu[base + 8];
                a[mf][2] = smu[base + 4 * 72];
                a[mf][3] = smu[base + 4 * 72 + 8];
            }
            uint32_t bf[4][2];
#pragma unroll
            for (int nf = 0; nf < 4; nf++) {
                int base = boff + krow * 264 + wn * 32 + nf * 8 + g;
                bf[nf][0] = smu[base];
                bf[nf][1] = smu[base + 4 * 264];
            }
#pragma unroll
            for (int mf = 0; mf < 4; mf++)
#pragma unroll
                for (int nf = 0; nf < 4; nf++)
                    mma_tf32(acc[mf][nf], a[mf], bf[nf]);
        }
    }

    __syncthreads();
    __half* Ts = (__half*)(sm + HG_B);           // [f=256][j=64], stride 72 halves
#pragma unroll
    for (int mf = 0; mf < 4; mf++) {
        const int r0 = mf * 16 + g;
        const float zi0 = sm[HG_ZI + r0], zi1 = sm[HG_ZI + r0 + 8];
#pragma unroll
        for (int nf = 0; nf < 4; nf++) {
            const int c0 = wn * 32 + nf * 8 + 2 * (lane & 3);
            Ts[(c0)     * 72 + r0]     = __float2half_rn(acc[mf][nf][0] * zi0);
            Ts[(c0 + 1) * 72 + r0]     = __float2half_rn(acc[mf][nf][1] * zi0);
            Ts[(c0)     * 72 + r0 + 8] = __float2half_rn(acc[mf][nf][2] * zi1);
            Ts[(c0 + 1) * 72 + r0 + 8] = __float2half_rn(acc[mf][nf][3] * zi1);
        }
    }
    __syncthreads();
    const int b = R0 >> 12, jloc = R0 & (NN - 1);
    __half* dst = g_hnT + ((size_t)b * FD + t) * NN + jloc;
    const uint4* srcv = (const uint4*)(Ts + t * 72);
#pragma unroll
    for (int q = 0; q < 8; q++)
        ((uint4*)dst)[q] = srcv[q];
}

// ---------------------------------------------------------------------------
// L4: out = elu( E' @ B' )  fp16 mma — frozen round-14 best (KC=128)
// ---------------------------------------------------------------------------
#define AT_STR 136                       // halves (128 data + 8 pad)
#define A_STG (128 * AT_STR)             // 17408 halves/stage
#define AT_B0 (2 * A_STG)                // 34816
#define B_STG (256 * AT_STR)             // 34816 halves/stage
#define AT_HALVES (AT_B0 + 2 * B_STG)    // 104448 halves = 204 KB

#define LOAD_B(stage, cc) do {                                                     \
    const __half* _src = hT + (size_t)fr * NN + (cc) * KC + sg * 64;               \
    uint32_t _dst = smb + (AT_B0 + (stage) * B_STG + fr * AT_STR) * 2 + sg * 128;  \
    _Pragma("unroll")                                                              \
    for (int _q = 0; _q < 8; _q++) cp16(_dst + _q * 16, _src + _q * 8);            \
    CP_COMMIT();                                                                   \
} while (0)

#define BUILD_A(stage, jbase, wbits) do {                                          \
    uint32_t _bits = (wbits);                                                      \
    __half* _sA = sh + (stage) * A_STG + ia * AT_STR + kh;                         \
    _Pragma("unroll")                                                              \
    for (int _h = 0; _h < 2; _h++) {                                               \
        float _ev[16];                                                             \
        _Pragma("unroll")                                                          \
        for (int _r = 0; _r < 16; _r++) {                                          \
            const int _jr = _h * 16 + _r;                                          \
            float _s = f1v + f2p[(jbase) + _jr];                                   \
            float _y = fmaxf(_s, 0.2f * _s) - cjp[(jbase) + _jr];                  \
            _ev[_r] = ((_bits >> _jr) & 1u) ? ex2(_y) : 0.f;                       \
        }                                                                          \
        __half2 _h2[8];                                                            \
        _Pragma("unroll")                                                          \
        for (int _p = 0; _p < 8; _p++) _h2[_p] = __floats2half2_rn(_ev[2*_p], _ev[2*_p+1]); \
        *(uint4*)(_sA + _h * 16)     = *(uint4*)(&_h2[0]);                         \
        *(uint4*)(_sA + _h * 16 + 8) = *(uint4*)(&_h2[4]);                         \
    }                                                                              \
} while (0)

__global__ void __launch_bounds__(512, 1) k_att(float* __restrict__ out) {
    extern __shared__ __half sh[];
    const uint32_t smb = smem_u32(sh);
    const int t = threadIdx.x, lane = t & 31, wid = t >> 5;
    const int wm = wid >> 2, wn = wid & 3;
    const int g = lane >> 2, c2 = lane & 3;
    const int b = blockIdx.y;
    const int i0 = blockIdx.x * 128;

    const int ia = t & 127;
    const int kh = (t >> 7) * 32;        // 0,32,64,96
    const int khw = kh >> 5;             // word 0..3 within chunk
    const uint32_t* aprow = g_adjp + (size_t)(b * NN + i0 + ia) * (NN / 32);
    const float* f2p = g_f2 + b * NN + kh;
    const float* cjp = g_c + b * NN + kh;
    const float f1v = g_f1[b * NN + i0 + ia];
    const __half* hT = g_hnT + (size_t)b * FD * NN;

    const int fr = t >> 1, sg = t & 1;

    const uint32_t aBase = smb + (uint32_t)((wm * 32 + (lane & 15)) * AT_STR + (lane >> 4) * 8) * 2;
    const uint32_t bBase = smb + (uint32_t)((wn * 64 + (lane & 7) + (lane >> 4) * 8) * AT_STR
                                            + ((lane >> 3) & 1) * 8) * 2;

    LOAD_B(0, 0);
    {
        uint32_t wb0 = aprow[khw];
        BUILD_A(0, 0, wb0);
    }
    CP_WAIT0();
    __syncthreads();

    float acc[2][8][4] = {};

    for (int c = 0; c < NCH; c++) {
        const int sc = c & 1;
        const bool pre = (c + 1 < NCH);

        uint32_t wbn = 0;
        if (pre) {
            LOAD_B(sc ^ 1, c + 1);
            wbn = aprow[(c + 1) * 4 + khw];
        }

        const uint32_t aS = aBase + sc * (A_STG * 2);
        const uint32_t bS = bBase + (AT_B0 + sc * B_STG) * 2;
#pragma unroll
        for (int kf = 0; kf < 8; kf++) {
            uint32_t af[2][4];
#pragma unroll
            for (int mf = 0; mf < 2; mf++)
                ldsm4(af[mf], aS + mf * (16 * AT_STR * 2) + kf * 32);
            uint32_t bf[4][4];
#pragma unroll
            for (int nfp = 0; nfp < 4; nfp++)
                ldsm4(bf[nfp], bS + nfp * (16 * AT_STR * 2) + kf * 32);
#pragma unroll
            for (int mf = 0; mf < 2; mf++)
#pragma unroll
                for (int nf = 0; nf < 8; nf++)
                    mma_f16(acc[mf][nf], af[mf], &bf[nf >> 1][(nf & 1) * 2]);
        }

        if (pre) {
            BUILD_A(sc ^ 1, (c + 1) * KC, wbn);
            CP_WAIT0();
            __syncthreads();
        }
    }

#pragma unroll
    for (int mf = 0; mf < 2; mf++) {
        const int r = i0 + wm * 32 + mf * 16 + g;
#pragma unroll
        for (int nf = 0; nf < 8; nf++) {
            const int col = wn * 64 + nf * 8 + 2 * c2;
            float2 p0 = make_float2(felu(acc[mf][nf][0]), felu(acc[mf][nf][1]));
            float2 p1 = make_float2(felu(acc[mf][nf][2]), felu(acc[mf][nf][3]));
            *(float2*)(out + ((size_t)(b * NN + r)) * FD + col) = p0;
            *(float2*)(out + ((size_t)(b * NN + r + 8)) * FD + col) = p1;
        }
    }
}

// ---------------------------------------------------------------------------
extern "C" void kernel_launch(void* const* d_in, const int* in_sizes, int n_in,
                              void* d_out, int out_size) {
    const float* input = (const float*)d_in[0];
    const int*   adj   = (const int*)d_in[1];
    const float* W     = (const float*)d_in[2];
    const float* a     = (const float*)d_in[3];
    float* out = (float*)d_out;

    cudaFuncSetAttribute(k_hgen, cudaFuncAttributeMaxDynamicSharedMemorySize, HG_FLOATS * 4);
    cudaFuncSetAttribute(k_att, cudaFuncAttributeMaxDynamicSharedMemorySize, AT_HALVES * 2);

    k_f12v<<<BSZ * NN / 64, 512>>>(input, W, a);                     // launch 1
    k_cmax<<<BSZ, 256>>>();                                          // launch 2
    k_Zc<<<dim3(NN / 128, ZSPLIT / 2, BSZ), 128>>>(adj, 0);          // launch 3
    k_Zc<<<dim3(NN / 128, ZSPLIT / 2, BSZ), 128>>>(adj, ZSPLIT / 2); // launch 4 (profiled)
    k_hgen<<<BSZ * NN / 64, 256, HG_FLOATS * 4>>>(input, W);         // launch 5
    k_att<<<dim3(NN / 128, BSZ), 512, AT_HALVES * 2>>>(out);         // launch 6
}

// round 16
// speedup vs baseline: 1.0719x; 1.0719x over previous
#include <cuda_runtime.h>
#include <cuda_fp16.h>
#include <cstdint>
#include <math.h>

#define BSZ 4
#define NN 4096
#define FD 256
#define KC 128
#define NCH (NN / KC)
#define ZSPLIT 32
#define LOG2E 1.4426950408889634f

// ---------------- scratch ----------------
__device__ __half g_hnT[BSZ * FD * NN];      // [b][f][j] = h[j,f]/S_j, fp16
__device__ float g_f1[BSZ * NN];
__device__ float g_f2[BSZ * NN];
__device__ float g_c[BSZ * NN];              // lrelu(maxf1 + f2_j), log2 units
__device__ float g_Zp[ZSPLIT][BSZ * NN];
__device__ uint32_t g_adjp[BSZ * NN * (NN / 32)];  // packed adj bits, 8MB
__device__ int g_mf1i[BSZ];                  // float-bits of max(0, max f1) (atomicMax)

// ---------------- helpers ----------------
__device__ __forceinline__ uint32_t smem_u32(const void* p) {
    uint32_t a;
    asm("{ .reg .u64 t; cvta.to.shared.u64 t, %1; cvt.u32.u64 %0, t; }" : "=r"(a) : "l"(p));
    return a;
}
__device__ __forceinline__ float tf32r(float x) {
    uint32_t r;
    asm("cvt.rna.tf32.f32 %0, %1;" : "=r"(r) : "f"(x));
    return __uint_as_float(r);
}
__device__ __forceinline__ float ex2(float y) {   // MUFU exp2
    float r;
    asm("ex2.approx.ftz.f32 %0, %1;" : "=f"(r) : "f"(y));
    return r;
}
__device__ __forceinline__ void cp16(uint32_t dst, const void* src) {
    asm volatile("cp.async.cg.shared.global [%0], [%1], 16;" :: "r"(dst), "l"(src));
}
#define CP_COMMIT() asm volatile("cp.async.commit_group;" ::: "memory")
#define CP_WAIT0()  asm volatile("cp.async.wait_group 0;" ::: "memory")

__device__ __forceinline__ float fexp2(float y) {  // FMA-pipe 2^y (epilogue)
    float yr = y + 12582912.0f;
    int n = __float_as_int(yr) - 0x4B400000;
    float r = y - (yr - 12582912.0f);
    float p = fmaf(0.0013333558f, r, 0.0096181291f);
    p = fmaf(p, r, 0.0555041086f);
    p = fmaf(p, r, 0.2402265069f);
    p = fmaf(p, r, 0.6931471806f);
    p = fmaf(p, r, 1.0f);
    return __int_as_float(__float_as_int(p) + (n << 23));
}
__device__ __forceinline__ float felu(float x) {
    float q = fmaf(0.0083333338f, x, 0.0416666679f);
    q = fmaf(q, x, 0.16666667f);
    q = fmaf(q, x, 0.5f);
    q = fmaf(q, x, 1.0f);
    float small = x * q;
    float big = fexp2(x * LOG2E) - 1.0f;
    float neg = (x >= -0.25f) ? small : big;
    return (x > 0.f) ? x : neg;
}
__device__ __forceinline__ void ldsm4(uint32_t* r, uint32_t addr) {
    asm volatile("ldmatrix.sync.aligned.m8n8.x4.shared.b16 {%0,%1,%2,%3}, [%4];"
                 : "=r"(r[0]), "=r"(r[1]), "=r"(r[2]), "=r"(r[3]) : "r"(addr));
}
__device__ __forceinline__ void mma_f16(float* d, const uint32_t* a, const uint32_t* b2) {
    asm volatile(
        "mma.sync.aligned.m16n8k16.row.col.f32.f16.f16.f32 "
        "{%0,%1,%2,%3}, {%4,%5,%6,%7}, {%8,%9}, {%0,%1,%2,%3};"
        : "+f"(d[0]), "+f"(d[1]), "+f"(d[2]), "+f"(d[3])
        : "r"(a[0]), "r"(a[1]), "r"(a[2]), "r"(a[3]), "r"(b2[0]), "r"(b2[1]));
}
__device__ __forceinline__ void mma_tf32(float* d, const uint32_t* a, const uint32_t* bb) {
    asm volatile(
        "mma.sync.aligned.m16n8k8.row.col.f32.tf32.tf32.f32 "
        "{%0,%1,%2,%3}, {%4,%5,%6,%7}, {%8,%9}, {%0,%1,%2,%3};"
        : "+f"(d[0]), "+f"(d[1]), "+f"(d[2]), "+f"(d[3])
        : "r"(a[0]), "r"(a[1]), "r"(a[2]), "r"(a[3]), "r"(bb[0]), "r"(bb[1]));
}

// ---------------------------------------------------------------------------
// L1: fused  v = (W@a)*log2e  +  f1 = X.v1, f2 = X.v2  +  block max -> atomicMax
// ---------------------------------------------------------------------------
__global__ __launch_bounds__(512) void k_f12v(const float* __restrict__ X,
                                              const float* __restrict__ W,
                                              const float* __restrict__ a) {
    __shared__ float sa[2 * FD];
    __shared__ float sv[2 * FD];
    __shared__ float smax[16];
    const int t = threadIdx.x, lane = t & 31, w = t >> 5;
    sa[t] = a[t];
    __syncthreads();
    if (t < FD) {
        float s1 = 0.f, s2 = 0.f;
        const float* wr = W + (size_t)t * FD;
#pragma unroll 4
        for (int f = 0; f < FD; f++) {
            float wv = wr[f];
            s1 = fmaf(wv, sa[f], s1);
            s2 = fmaf(wv, sa[FD + f], s2);
        }
        sv[t] = s1 * LOG2E;
        sv[FD + t] = s2 * LOG2E;
    }
    __syncthreads();
    const int R0 = blockIdx.x * 64;
    float mloc = 0.f;                       // bound = max(0, row sums)
#pragma unroll
    for (int rr = 0; rr < 4; rr++) {
        const int row = R0 + w * 4 + rr;
        const float* xr = X + (size_t)row * FD;
        float s1 = 0.f, s2 = 0.f;
#pragma unroll
        for (int k = lane; k < FD; k += 32) {
            float xv = xr[k];
            s1 = fmaf(xv, sv[k], s1);
            s2 = fmaf(xv, sv[FD + k], s2);
        }
#pragma unroll
        for (int o = 16; o; o >>= 1) {
            s1 += __shfl_xor_sync(~0u, s1, o);
            s2 += __shfl_xor_sync(~0u, s2, o);
        }
        mloc = fmaxf(mloc, s1);
        if (lane == 0) { g_f1[row] = s1; g_f2[row] = s2; }
    }
    // block max (one atomic per block; idempotent across graph replays)
    if (lane == 0) smax[w] = mloc;
    __syncthreads();
    if (w == 0) {
        float m = (lane < 16) ? smax[lane] : 0.f;
#pragma unroll
        for (int o = 16; o; o >>= 1) m = fmaxf(m, __shfl_xor_sync(~0u, m, o));
        if (lane == 0) atomicMax(&g_mf1i[R0 >> 12], __float_as_int(m));
    }
}

// ---------------------------------------------------------------------------
// L2: shifted partial sums + adj bit-packing (c_j inline from g_mf1)
//   grid (NN/128, ZSPLIT, BSZ), 128 threads
// ---------------------------------------------------------------------------
__global__ __launch_bounds__(128) void k_Zc(const int* __restrict__ adj) {
    const int b = blockIdx.z;
    const int tid = threadIdx.x;
    const int j = blockIdx.x * 128 + tid;
    const int split = blockIdx.y;
    const int ilen = NN / ZSPLIT;
    const int i0 = split * ilen;
    const int wq = blockIdx.x * 4 + (tid >> 5);
    const int wl = tid & 31;

    const float mf = __int_as_float(g_mf1i[b]);
    const float f2j = g_f2[b * NN + j];
    float s0 = mf + f2j;
    const float cj = fmaxf(s0, 0.2f * s0);
    if (split == 0) g_c[b * NN + j] = cj;

    const int* ap = adj + ((size_t)b * NN + i0) * NN + j;
    const float* f1p = g_f1 + b * NN + i0;
    uint32_t* pk = g_adjp + (size_t)(b * NN + i0) * (NN / 32) + wq;
    float acc = 0.f;
#pragma unroll 16
    for (int i = 0; i < ilen; i++) {
        int mm = ap[(size_t)i * NN];
        uint32_t blt = __ballot_sync(~0u, mm > 0);
        if (wl == 0) pk[(size_t)i * (NN / 32)] = blt;
        float y = f1p[i] + f2j;
        y = fmaxf(y, 0.2f * y) - cj;
        float e = ex2(y);
        acc += (mm > 0) ? e : 0.f;
    }
    g_Zp[split][b * NN + j] = acc;
}

// ---------------------------------------------------------------------------
// L3: hnT[b][f][j] = fp16( (X@W)[j,f] / S_j )  via tf32 mma + smem transpose
// ---------------------------------------------------------------------------
#define HG_ZI 0
#define HG_A 64
#define HG_ASTG (32 * 72)
#define HG_B (64 + 2 * HG_ASTG)
#define HG_BSTG (32 * 264)
#define HG_FLOATS (HG_B + 2 * HG_BSTG)
__global__ void __launch_bounds__(256, 2) k_hgen(const float* __restrict__ X,
                                                 const float* __restrict__ W) {
    extern __shared__ float sm[];
    const uint32_t smb = smem_u32(sm);
    const int t = threadIdx.x, lane = t & 31, wn = t >> 5, g = lane >> 2;
    const int R0 = blockIdx.x * 64;
    const int ia = t & 63, kh = (t >> 6) * 8;
    const int kb = t >> 3, seg = t & 7;

    if (t < 64) {
        float z = 0.f;
#pragma unroll
        for (int s = 0; s < ZSPLIT; s++) z += g_Zp[s][R0 + t];
        sm[HG_ZI + t] = 1.0f / z;
    }

    const float* xrow = X + (size_t)(R0 + ia) * FD + kh;
    {
        const float* src = W + (size_t)kb * FD + seg * 4;
        uint32_t dst = smb + (HG_B + kb * 264 + seg * 4) * 4;
#pragma unroll
        for (int q = 0; q < 8; q++) cp16(dst + q * 128, src + q * 32);
        CP_COMMIT();
    }

    float acc[4][4][4] = {};
    for (int c = 0; c < 8; c++) {
        const int aoff = HG_A + (c & 1) * HG_ASTG;
        const int boff = HG_B + (c & 1) * HG_BSTG;
        float4 x0 = *(const float4*)(xrow + c * 32);
        float4 x1 = *(const float4*)(xrow + c * 32 + 4);
        float e[8] = {x0.x, x0.y, x0.z, x0.w, x1.x, x1.y, x1.z, x1.w};
#pragma unroll
        for (int q = 0; q < 8; q++)
            sm[aoff + (kh + q) * 72 + ia] = tf32r(e[q]);
        CP_WAIT0();
        __syncthreads();
        if (c < 7) {
            const float* src = W + (size_t)((c + 1) * 32 + kb) * FD + seg * 4;
            uint32_t dst = smb + (HG_B + ((c + 1) & 1) * HG_BSTG + kb * 264 + seg * 4) * 4;
#pragma unroll
            for (int q = 0; q < 8; q++) cp16(dst + q * 128, src + q * 32);
            CP_COMMIT();
        }
        const uint32_t* smu = (const uint32_t*)sm;
#pragma unroll
        for (int kf = 0; kf < 4; kf++) {
            const int krow = kf * 8 + (lane & 3);
            uint32_t a[4][4];
#pragma unroll
            for (int mf = 0; mf < 4; mf++) {
                int base = aoff + krow * 72 + mf * 16 + g;
                a[mf][0] = smu[base];
                a[mf][1] = smu[base + 8];
                a[mf][2] = smu[base + 4 * 72];
                a[mf][3] = smu[base + 4 * 72 + 8];
            }
            uint32_t bf[4][2];
#pragma unroll
            for (int nf = 0; nf < 4; nf++) {
                int base = boff + krow * 264 + wn * 32 + nf * 8 + g;
                bf[nf][0] = smu[base];
                bf[nf][1] = smu[base + 4 * 264];
            }
#pragma unroll
            for (int mf = 0; mf < 4; mf++)
#pragma unroll
                for (int nf = 0; nf < 4; nf++)
                    mma_tf32(acc[mf][nf], a[mf], bf[nf]);
        }
    }

    __syncthreads();
    __half* Ts = (__half*)(sm + HG_B);           // [f=256][j=64], stride 72 halves
#pragma unroll
    for (int mf = 0; mf < 4; mf++) {
        const int r0 = mf * 16 + g;
        const float zi0 = sm[HG_ZI + r0], zi1 = sm[HG_ZI + r0 + 8];
#pragma unroll
        for (int nf = 0; nf < 4; nf++) {
            const int c0 = wn * 32 + nf * 8 + 2 * (lane & 3);
            Ts[(c0)     * 72 + r0]     = __float2half_rn(acc[mf][nf][0] * zi0);
            Ts[(c0 + 1) * 72 + r0]     = __float2half_rn(acc[mf][nf][1] * zi0);
            Ts[(c0)     * 72 + r0 + 8] = __float2half_rn(acc[mf][nf][2] * zi1);
            Ts[(c0 + 1) * 72 + r0 + 8] = __float2half_rn(acc[mf][nf][3] * zi1);
        }
    }
    __syncthreads();
    const int b = R0 >> 12, jloc = R0 & (NN - 1);
    __half* dst = g_hnT + ((size_t)b * FD + t) * NN + jloc;
    const uint4* srcv = (const uint4*)(Ts + t * 72);
#pragma unroll
    for (int q = 0; q < 8; q++)
        ((uint4*)dst)[q] = srcv[q];
}

// ---------------------------------------------------------------------------
// L4: out = elu( E' @ B' )  fp16 mma — frozen round-14 best (KC=128)
// ---------------------------------------------------------------------------
#define AT_STR 136                       // halves (128 data + 8 pad)
#define A_STG (128 * AT_STR)             // 17408 halves/stage
#define AT_B0 (2 * A_STG)                // 34816
#define B_STG (256 * AT_STR)             // 34816 halves/stage
#define AT_HALVES (AT_B0 + 2 * B_STG)    // 104448 halves = 204 KB

#define LOAD_B(stage, cc) do {                                                     \
    const __half* _src = hT + (size_t)fr * NN + (cc) * KC + sg * 64;               \
    uint32_t _dst = smb + (AT_B0 + (stage) * B_STG + fr * AT_STR) * 2 + sg * 128;  \
    _Pragma("unroll")                                                              \
    for (int _q = 0; _q < 8; _q++) cp16(_dst + _q * 16, _src + _q * 8);            \
    CP_COMMIT();                                                                   \
} while (0)

#define BUILD_A(stage, jbase, wbits) do {                                          \
    uint32_t _bits = (wbits);                                                      \
    __half* _sA = sh + (stage) * A_STG + ia * AT_STR + kh;                         \
    _Pragma("unroll")                                                              \
    for (int _h = 0; _h < 2; _h++) {                                               \
        float _ev[16];                                                             \
        _Pragma("unroll")                                                          \
        for (int _r = 0; _r < 16; _r++) {                                          \
            const int _jr = _h * 16 + _r;                                          \
            float _s = f1v + f2p[(jbase) + _jr];                                   \
            float _y = fmaxf(_s, 0.2f * _s) - cjp[(jbase) + _jr];                  \
            _ev[_r] = ((_bits >> _jr) & 1u) ? ex2(_y) : 0.f;                       \
        }                                                                          \
        __half2 _h2[8];                                                            \
        _Pragma("unroll")                                                          \
        for (int _p = 0; _p < 8; _p++) _h2[_p] = __floats2half2_rn(_ev[2*_p], _ev[2*_p+1]); \
        *(uint4*)(_sA + _h * 16)     = *(uint4*)(&_h2[0]);                         \
        *(uint4*)(_sA + _h * 16 + 8) = *(uint4*)(&_h2[4]);                         \
    }                                                                              \
} while (0)

__global__ void __launch_bounds__(512, 1) k_att(float* __restrict__ out) {
    extern __shared__ __half sh[];
    const uint32_t smb = smem_u32(sh);
    const int t = threadIdx.x, lane = t & 31, wid = t >> 5;
    const int wm = wid >> 2, wn = wid & 3;
    const int g = lane >> 2, c2 = lane & 3;
    const int b = blockIdx.y;
    const int i0 = blockIdx.x * 128;

    const int ia = t & 127;
    const int kh = (t >> 7) * 32;        // 0,32,64,96
    const int khw = kh >> 5;             // word 0..3 within chunk
    const uint32_t* aprow = g_adjp + (size_t)(b * NN + i0 + ia) * (NN / 32);
    const float* f2p = g_f2 + b * NN + kh;
    const float* cjp = g_c + b * NN + kh;
    const float f1v = g_f1[b * NN + i0 + ia];
    const __half* hT = g_hnT + (size_t)b * FD * NN;

    const int fr = t >> 1, sg = t & 1;

    const uint32_t aBase = smb + (uint32_t)((wm * 32 + (lane & 15)) * AT_STR + (lane >> 4) * 8) * 2;
    const uint32_t bBase = smb + (uint32_t)((wn * 64 + (lane & 7) + (lane >> 4) * 8) * AT_STR
                                            + ((lane >> 3) & 1) * 8) * 2;

    LOAD_B(0, 0);
    {
        uint32_t wb0 = aprow[khw];
        BUILD_A(0, 0, wb0);
    }
    CP_WAIT0();
    __syncthreads();

    float acc[2][8][4] = {};

    for (int c = 0; c < NCH; c++) {
        const int sc = c & 1;
        const bool pre = (c + 1 < NCH);

        uint32_t wbn = 0;
        if (pre) {
            LOAD_B(sc ^ 1, c + 1);
            wbn = aprow[(c + 1) * 4 + khw];
        }

        const uint32_t aS = aBase + sc * (A_STG * 2);
        const uint32_t bS = bBase + (AT_B0 + sc * B_STG) * 2;
#pragma unroll
        for (int kf = 0; kf < 8; kf++) {
            uint32_t af[2][4];
#pragma unroll
            for (int mf = 0; mf < 2; mf++)
                ldsm4(af[mf], aS + mf * (16 * AT_STR * 2) + kf * 32);
            uint32_t bf[4][4];
#pragma unroll
            for (int nfp = 0; nfp < 4; nfp++)
                ldsm4(bf[nfp], bS + nfp * (16 * AT_STR * 2) + kf * 32);
#pragma unroll
            for (int mf = 0; mf < 2; mf++)
#pragma unroll
                for (int nf = 0; nf < 8; nf++)
                    mma_f16(acc[mf][nf], af[mf], &bf[nf >> 1][(nf & 1) * 2]);
        }

        if (pre) {
            BUILD_A(sc ^ 1, (c + 1) * KC, wbn);
            CP_WAIT0();
            __syncthreads();
        }
    }

#pragma unroll
    for (int mf = 0; mf < 2; mf++) {
        const int r = i0 + wm * 32 + mf * 16 + g;
#pragma unroll
        for (int nf = 0; nf < 8; nf++) {
            const int col = wn * 64 + nf * 8 + 2 * c2;
            float2 p0 = make_float2(felu(acc[mf][nf][0]), felu(acc[mf][nf][1]));
            float2 p1 = make_float2(felu(acc[mf][nf][2]), felu(acc[mf][nf][3]));
            *(float2*)(out + ((size_t)(b * NN + r)) * FD + col) = p0;
            *(float2*)(out + ((size_t)(b * NN + r + 8)) * FD + col) = p1;
        }
    }
}

// ---------------------------------------------------------------------------
extern "C" void kernel_launch(void* const* d_in, const int* in_sizes, int n_in,
                              void* d_out, int out_size) {
    const float* input = (const float*)d_in[0];
    const int*   adj   = (const int*)d_in[1];
    const float* W     = (const float*)d_in[2];
    const float* a     = (const float*)d_in[3];
    float* out = (float*)d_out;

    cudaFuncSetAttribute(k_hgen, cudaFuncAttributeMaxDynamicSharedMemorySize, HG_FLOATS * 4);
    cudaFuncSetAttribute(k_att, cudaFuncAttributeMaxDynamicSharedMemorySize, AT_HALVES * 2);

    k_f12v<<<BSZ * NN / 64, 512>>>(input, W, a);               // launch 1
    k_Zc<<<dim3(NN / 128, ZSPLIT, BSZ), 128>>>(adj);           // launch 2
    k_hgen<<<BSZ * NN / 64, 256, HG_FLOATS * 4>>>(input, W);   // launch 3
    k_att<<<dim3(NN / 128, BSZ), 512, AT_HALVES * 2>>>(out);   // launch 4 (profiled)
}

// round 17
// speedup vs baseline: 1.0886x; 1.0156x over previous
#include <cuda_runtime.h>
#include <cuda_fp16.h>
#include <cstdint>
#include <math.h>

#define BSZ 4
#define NN 4096
#define FD 256
#define KC 128
#define NCH (NN / KC)
#define ZSPLIT 32
#define LOG2E 1.4426950408889634f

// ---------------- scratch ----------------
__device__ __half g_hnT[BSZ * FD * NN];      // [b][f][j] = h[j,f]/S_j, fp16
__device__ float g_f1[BSZ * NN];
__device__ float g_f2[BSZ * NN];
__device__ float g_c[BSZ * NN];              // lrelu(maxf1 + f2_j), log2 units
__device__ float g_Zp[ZSPLIT][BSZ * NN];
__device__ uint32_t g_adjp[BSZ * NN * (NN / 32)];  // packed adj bits, 8MB
__device__ int g_mf1i[BSZ];                  // float-bits of max(0, max f1)

// ---------------- helpers ----------------
__device__ __forceinline__ uint32_t smem_u32(const void* p) {
    uint32_t a;
    asm("{ .reg .u64 t; cvta.to.shared.u64 t, %1; cvt.u32.u64 %0, t; }" : "=r"(a) : "l"(p));
    return a;
}
__device__ __forceinline__ float tf32r(float x) {
    uint32_t r;
    asm("cvt.rna.tf32.f32 %0, %1;" : "=r"(r) : "f"(x));
    return __uint_as_float(r);
}
__device__ __forceinline__ float ex2(float y) {   // MUFU exp2
    float r;
    asm("ex2.approx.ftz.f32 %0, %1;" : "=f"(r) : "f"(y));
    return r;
}
__device__ __forceinline__ void cp16(uint32_t dst, const void* src) {
    asm volatile("cp.async.cg.shared.global [%0], [%1], 16;" :: "r"(dst), "l"(src));
}
#define CP_COMMIT() asm volatile("cp.async.commit_group;" ::: "memory")
#define CP_WAIT0()  asm volatile("cp.async.wait_group 0;" ::: "memory")

__device__ __forceinline__ float fexp2(float y) {  // FMA-pipe 2^y (epilogue)
    float yr = y + 12582912.0f;
    int n = __float_as_int(yr) - 0x4B400000;
    float r = y - (yr - 12582912.0f);
    float p = fmaf(0.0013333558f, r, 0.0096181291f);
    p = fmaf(p, r, 0.0555041086f);
    p = fmaf(p, r, 0.2402265069f);
    p = fmaf(p, r, 0.6931471806f);
    p = fmaf(p, r, 1.0f);
    return __int_as_float(__float_as_int(p) + (n << 23));
}
__device__ __forceinline__ float felu(float x) {
    float q = fmaf(0.0083333338f, x, 0.0416666679f);
    q = fmaf(q, x, 0.16666667f);
    q = fmaf(q, x, 0.5f);
    q = fmaf(q, x, 1.0f);
    float small = x * q;
    float big = fexp2(x * LOG2E) - 1.0f;
    float neg = (x >= -0.25f) ? small : big;
    return (x > 0.f) ? x : neg;
}
__device__ __forceinline__ void ldsm4(uint32_t* r, uint32_t addr) {
    asm volatile("ldmatrix.sync.aligned.m8n8.x4.shared.b16 {%0,%1,%2,%3}, [%4];"
                 : "=r"(r[0]), "=r"(r[1]), "=r"(r[2]), "=r"(r[3]) : "r"(addr));
}
__device__ __forceinline__ void mma_f16(float* d, const uint32_t* a, const uint32_t* b2) {
    asm volatile(
        "mma.sync.aligned.m16n8k16.row.col.f32.f16.f16.f32 "
        "{%0,%1,%2,%3}, {%4,%5,%6,%7}, {%8,%9}, {%0,%1,%2,%3};"
        : "+f"(d[0]), "+f"(d[1]), "+f"(d[2]), "+f"(d[3])
        : "r"(a[0]), "r"(a[1]), "r"(a[2]), "r"(a[3]), "r"(b2[0]), "r"(b2[1]));
}
__device__ __forceinline__ void mma_tf32(float* d, const uint32_t* a, const uint32_t* bb) {
    asm volatile(
        "mma.sync.aligned.m16n8k8.row.col.f32.tf32.tf32.f32 "
        "{%0,%1,%2,%3}, {%4,%5,%6,%7}, {%8,%9}, {%0,%1,%2,%3};"
        : "+f"(d[0]), "+f"(d[1]), "+f"(d[2]), "+f"(d[3])
        : "r"(a[0]), "r"(a[1]), "r"(a[2]), "r"(a[3]), "r"(bb[0]), "r"(bb[1]));
}

// ---------------------------------------------------------------------------
// L1: fused  v = (W@a)*log2e  +  f1 = X.v1, f2 = X.v2  +  block max -> atomicMax
// ---------------------------------------------------------------------------
__global__ __launch_bounds__(512) void k_f12v(const float* __restrict__ X,
                                              const float* __restrict__ W,
                                              const float* __restrict__ a) {
    __shared__ float sa[2 * FD];
    __shared__ float sv[2 * FD];
    __shared__ float smax[16];
    const int t = threadIdx.x, lane = t & 31, w = t >> 5;
    sa[t] = a[t];
    __syncthreads();
    if (t < FD) {
        float s1 = 0.f, s2 = 0.f;
        const float* wr = W + (size_t)t * FD;
#pragma unroll 4
        for (int f = 0; f < FD; f++) {
            float wv = wr[f];
            s1 = fmaf(wv, sa[f], s1);
            s2 = fmaf(wv, sa[FD + f], s2);
        }
        sv[t] = s1 * LOG2E;
        sv[FD + t] = s2 * LOG2E;
    }
    __syncthreads();
    const int R0 = blockIdx.x * 64;
    float mloc = 0.f;
#pragma unroll
    for (int rr = 0; rr < 4; rr++) {
        const int row = R0 + w * 4 + rr;
        const float* xr = X + (size_t)row * FD;
        float s1 = 0.f, s2 = 0.f;
#pragma unroll
        for (int k = lane; k < FD; k += 32) {
            float xv = xr[k];
            s1 = fmaf(xv, sv[k], s1);
            s2 = fmaf(xv, sv[FD + k], s2);
        }
#pragma unroll
        for (int o = 16; o; o >>= 1) {
            s1 += __shfl_xor_sync(~0u, s1, o);
            s2 += __shfl_xor_sync(~0u, s2, o);
        }
        mloc = fmaxf(mloc, s1);
        if (lane == 0) { g_f1[row] = s1; g_f2[row] = s2; }
    }
    if (lane == 0) smax[w] = mloc;
    __syncthreads();
    if (w == 0) {
        float m = (lane < 16) ? smax[lane] : 0.f;
#pragma unroll
        for (int o = 16; o; o >>= 1) m = fmaxf(m, __shfl_xor_sync(~0u, m, o));
        if (lane == 0) atomicMax(&g_mf1i[R0 >> 12], __float_as_int(m));
    }
}

// ---------------------------------------------------------------------------
// L2: shifted partial sums + adj bit-packing (c_j inline from g_mf1)
// ---------------------------------------------------------------------------
__global__ __launch_bounds__(128) void k_Zc(const int* __restrict__ adj) {
    const int b = blockIdx.z;
    const int tid = threadIdx.x;
    const int j = blockIdx.x * 128 + tid;
    const int split = blockIdx.y;
    const int ilen = NN / ZSPLIT;
    const int i0 = split * ilen;
    const int wq = blockIdx.x * 4 + (tid >> 5);
    const int wl = tid & 31;

    const float mf = __int_as_float(g_mf1i[b]);
    const float f2j = g_f2[b * NN + j];
    float s0 = mf + f2j;
    const float cj = fmaxf(s0, 0.2f * s0);
    if (split == 0) g_c[b * NN + j] = cj;

    const int* ap = adj + ((size_t)b * NN + i0) * NN + j;
    const float* f1p = g_f1 + b * NN + i0;
    uint32_t* pk = g_adjp + (size_t)(b * NN + i0) * (NN / 32) + wq;
    float acc = 0.f;
#pragma unroll 16
    for (int i = 0; i < ilen; i++) {
        int mm = ap[(size_t)i * NN];
        uint32_t blt = __ballot_sync(~0u, mm > 0);
        if (wl == 0) pk[(size_t)i * (NN / 32)] = blt;
        float y = f1p[i] + f2j;
        y = fmaxf(y, 0.2f * y) - cj;
        float e = ex2(y);
        acc += (mm > 0) ? e : 0.f;
    }
    g_Zp[split][b * NN + j] = acc;
}

// ---------------------------------------------------------------------------
// L3: hnT[b][f][j] = fp16( (X@W)[j,f] / S_j )  via tf32 mma + smem transpose
// ---------------------------------------------------------------------------
#define HG_ZI 0
#define HG_A 64
#define HG_ASTG (32 * 72)
#define HG_B (64 + 2 * HG_ASTG)
#define HG_BSTG (32 * 264)
#define HG_FLOATS (HG_B + 2 * HG_BSTG)
__global__ void __launch_bounds__(256, 2) k_hgen(const float* __restrict__ X,
                                                 const float* __restrict__ W) {
    extern __shared__ float sm[];
    const uint32_t smb = smem_u32(sm);
    const int t = threadIdx.x, lane = t & 31, wn = t >> 5, g = lane >> 2;
    const int R0 = blockIdx.x * 64;
    const int ia = t & 63, kh = (t >> 6) * 8;
    const int kb = t >> 3, seg = t & 7;

    if (t < 64) {
        float z = 0.f;
#pragma unroll
        for (int s = 0; s < ZSPLIT; s++) z += g_Zp[s][R0 + t];
        sm[HG_ZI + t] = 1.0f / z;
    }

    const float* xrow = X + (size_t)(R0 + ia) * FD + kh;
    {
        const float* src = W + (size_t)kb * FD + seg * 4;
        uint32_t dst = smb + (HG_B + kb * 264 + seg * 4) * 4;
#pragma unroll
        for (int q = 0; q < 8; q++) cp16(dst + q * 128, src + q * 32);
        CP_COMMIT();
    }

    float acc[4][4][4] = {};
    for (int c = 0; c < 8; c++) {
        const int aoff = HG_A + (c & 1) * HG_ASTG;
        const int boff = HG_B + (c & 1) * HG_BSTG;
        float4 x0 = *(const float4*)(xrow + c * 32);
        float4 x1 = *(const float4*)(xrow + c * 32 + 4);
        float e[8] = {x0.x, x0.y, x0.z, x0.w, x1.x, x1.y, x1.z, x1.w};
#pragma unroll
        for (int q = 0; q < 8; q++)
            sm[aoff + (kh + q) * 72 + ia] = tf32r(e[q]);
        CP_WAIT0();
        __syncthreads();
        if (c < 7) {
            const float* src = W + (size_t)((c + 1) * 32 + kb) * FD + seg * 4;
            uint32_t dst = smb + (HG_B + ((c + 1) & 1) * HG_BSTG + kb * 264 + seg * 4) * 4;
#pragma unroll
            for (int q = 0; q < 8; q++) cp16(dst + q * 128, src + q * 32);
            CP_COMMIT();
        }
        const uint32_t* smu = (const uint32_t*)sm;
#pragma unroll
        for (int kf = 0; kf < 4; kf++) {
            const int krow = kf * 8 + (lane & 3);
            uint32_t a[4][4];
#pragma unroll
            for (int mf = 0; mf < 4; mf++) {
                int base = aoff + krow * 72 + mf * 16 + g;
                a[mf][0] = smu[base];
                a[mf][1] = smu[base + 8];
                a[mf][2] = smu[base + 4 * 72];
                a[mf][3] = smu[base + 4 * 72 + 8];
            }
            uint32_t bf[4][2];
#pragma unroll
            for (int nf = 0; nf < 4; nf++) {
                int base = boff + krow * 264 + wn * 32 + nf * 8 + g;
                bf[nf][0] = smu[base];
                bf[nf][1] = smu[base + 4 * 264];
            }
#pragma unroll
            for (int mf = 0; mf < 4; mf++)
#pragma unroll
                for (int nf = 0; nf < 4; nf++)
                    mma_tf32(acc[mf][nf], a[mf], bf[nf]);
        }
    }

    __syncthreads();
    __half* Ts = (__half*)(sm + HG_B);           // [f=256][j=64], stride 72 halves
#pragma unroll
    for (int mf = 0; mf < 4; mf++) {
        const int r0 = mf * 16 + g;
        const float zi0 = sm[HG_ZI + r0], zi1 = sm[HG_ZI + r0 + 8];
#pragma unroll
        for (int nf = 0; nf < 4; nf++) {
            const int c0 = wn * 32 + nf * 8 + 2 * (lane & 3);
            Ts[(c0)     * 72 + r0]     = __float2half_rn(acc[mf][nf][0] * zi0);
            Ts[(c0 + 1) * 72 + r0]     = __float2half_rn(acc[mf][nf][1] * zi0);
            Ts[(c0)     * 72 + r0 + 8] = __float2half_rn(acc[mf][nf][2] * zi1);
            Ts[(c0 + 1) * 72 + r0 + 8] = __float2half_rn(acc[mf][nf][3] * zi1);
        }
    }
    __syncthreads();
    const int b = R0 >> 12, jloc = R0 & (NN - 1);
    __half* dst = g_hnT + ((size_t)b * FD + t) * NN + jloc;
    const uint4* srcv = (const uint4*)(Ts + t * 72);
#pragma unroll
    for (int q = 0; q < 8; q++)
        ((uint4*)dst)[q] = srcv[q];
}

// ---------------------------------------------------------------------------
// L4: out = elu( E' @ B' )  fp16 mma — KC=128, staggered kf schedule,
//   vectorized scalar loads in the A build.
// ---------------------------------------------------------------------------
#define AT_STR 136                       // halves (128 data + 8 pad)
#define A_STG (128 * AT_STR)             // 17408 halves/stage
#define AT_B0 (2 * A_STG)                // 34816
#define B_STG (256 * AT_STR)             // 34816 halves/stage
#define AT_HALVES (AT_B0 + 2 * B_STG)    // 104448 halves = 204 KB

#define LOAD_B(stage, cc) do {                                                     \
    const __half* _src = hT + (size_t)fr * NN + (cc) * KC + sg * 64;               \
    uint32_t _dst = smb + (AT_B0 + (stage) * B_STG + fr * AT_STR) * 2 + sg * 128;  \
    _Pragma("unroll")                                                              \
    for (int _q = 0; _q < 8; _q++) cp16(_dst + _q * 16, _src + _q * 8);            \
    CP_COMMIT();                                                                   \
} while (0)

// thread builds 32 j (one packed word) of one of 128 rows; float4 scalar loads
#define BUILD_A(stage, jbase, wbits) do {                                          \
    uint32_t _bits = (wbits);                                                      \
    __half* _sA = sh + (stage) * A_STG + ia * AT_STR + kh;                         \
    _Pragma("unroll")                                                              \
    for (int _h = 0; _h < 2; _h++) {                                               \
        __half2 _h2[8];                                                            \
        _Pragma("unroll")                                                          \
        for (int _q = 0; _q < 4; _q++) {                                           \
            const int _jb = _h * 16 + _q * 4;                                      \
            float4 _f4 = *(const float4*)(f2p + (jbase) + _jb);                    \
            float4 _c4 = *(const float4*)(cjp + (jbase) + _jb);                    \
            float _fv[4] = {_f4.x, _f4.y, _f4.z, _f4.w};                           \
            float _cv[4] = {_c4.x, _c4.y, _c4.z, _c4.w};                           \
            float _ev[4];                                                          \
            _Pragma("unroll")                                                      \
            for (int _r = 0; _r < 4; _r++) {                                       \
                float _s = f1v + _fv[_r];                                          \
                float _y = fmaxf(_s, 0.2f * _s) - _cv[_r];                         \
                _ev[_r] = ((_bits >> (_jb + _r)) & 1u) ? ex2(_y) : 0.f;            \
            }                                                                      \
            _h2[_q * 2]     = __floats2half2_rn(_ev[0], _ev[1]);                   \
            _h2[_q * 2 + 1] = __floats2half2_rn(_ev[2], _ev[3]);                   \
        }                                                                          \
        *(uint4*)(_sA + _h * 16)     = *(uint4*)(&_h2[0]);                         \
        *(uint4*)(_sA + _h * 16 + 8) = *(uint4*)(&_h2[4]);                         \
    }                                                                              \
} while (0)

__global__ void __launch_bounds__(512, 1) k_att(float* __restrict__ out) {
    extern __shared__ __half sh[];
    const uint32_t smb = smem_u32(sh);
    const int t = threadIdx.x, lane = t & 31, wid = t >> 5;
    const int wm = wid >> 2, wn = wid & 3;
    const int g = lane >> 2, c2 = lane & 3;
    const int b = blockIdx.y;
    const int i0 = blockIdx.x * 128;

    const int ia = t & 127;
    const int kh = (t >> 7) * 32;        // 0,32,64,96
    const int khw = kh >> 5;             // word 0..3 within chunk
    const uint32_t* aprow = g_adjp + (size_t)(b * NN + i0 + ia) * (NN / 32);
    const float* f2p = g_f2 + b * NN + kh;
    const float* cjp = g_c + b * NN + kh;
    const float f1v = g_f1[b * NN + i0 + ia];
    const __half* hT = g_hnT + (size_t)b * FD * NN;

    const int fr = t >> 1, sg = t & 1;

    // per-warp-group kf stagger: the 4 warps sharing an SMSP start at
    // different k-fragments so ldsm and HMMA phases interleave across warps
    const int koff = (wid >> 2) * 2;

    const uint32_t aBase = smb + (uint32_t)((wm * 32 + (lane & 15)) * AT_STR + (lane >> 4) * 8) * 2;
    const uint32_t bBase = smb + (uint32_t)((wn * 64 + (lane & 7) + (lane >> 4) * 8) * AT_STR
                                            + ((lane >> 3) & 1) * 8) * 2;

    LOAD_B(0, 0);
    {
        uint32_t wb0 = aprow[khw];
        BUILD_A(0, 0, wb0);
    }
    CP_WAIT0();
    __syncthreads();

    float acc[2][8][4] = {};

    for (int c = 0; c < NCH; c++) {
        const int sc = c & 1;
        const bool pre = (c + 1 < NCH);

        uint32_t wbn = 0;
        if (pre) {
            LOAD_B(sc ^ 1, c + 1);
            wbn = aprow[(c + 1) * 4 + khw];
        }

        const uint32_t aS = aBase + sc * (A_STG * 2);
        const uint32_t bS = bBase + (AT_B0 + sc * B_STG) * 2;
#pragma unroll
        for (int kk = 0; kk < 8; kk++) {
            const int kf = (kk + koff) & 7;
            uint32_t af[2][4];
#pragma unroll
            for (int mf = 0; mf < 2; mf++)
                ldsm4(af[mf], aS + mf * (16 * AT_STR * 2) + kf * 32);
            uint32_t bf[4][4];
#pragma unroll
            for (int nfp = 0; nfp < 4; nfp++)
                ldsm4(bf[nfp], bS + nfp * (16 * AT_STR * 2) + kf * 32);
#pragma unroll
            for (int mf = 0; mf < 2; mf++)
#pragma unroll
                for (int nf = 0; nf < 8; nf++)
                    mma_f16(acc[mf][nf], af[mf], &bf[nf >> 1][(nf & 1) * 2]);
        }

        if (pre) {
            BUILD_A(sc ^ 1, (c + 1) * KC, wbn);
            CP_WAIT0();
            __syncthreads();
        }
    }

#pragma unroll
    for (int mf = 0; mf < 2; mf++) {
        const int r = i0 + wm * 32 + mf * 16 + g;
#pragma unroll
        for (int nf = 0; nf < 8; nf++) {
            const int col = wn * 64 + nf * 8 + 2 * c2;
            float2 p0 = make_float2(felu(acc[mf][nf][0]), felu(acc[mf][nf][1]));
            float2 p1 = make_float2(felu(acc[mf][nf][2]), felu(acc[mf][nf][3]));
            *(float2*)(out + ((size_t)(b * NN + r)) * FD + col) = p0;
            *(float2*)(out + ((size_t)(b * NN + r + 8)) * FD + col) = p1;
        }
    }
}

// ---------------------------------------------------------------------------
extern "C" void kernel_launch(void* const* d_in, const int* in_sizes, int n_in,
                              void* d_out, int out_size) {
    const float* input = (const float*)d_in[0];
    const int*   adj   = (const int*)d_in[1];
    const float* W     = (const float*)d_in[2];
    const float* a     = (const float*)d_in[3];
    float* out = (float*)d_out;

    cudaFuncSetAttribute(k_hgen, cudaFuncAttributeMaxDynamicSharedMemorySize, HG_FLOATS * 4);
    cudaFuncSetAttribute(k_att, cudaFuncAttributeMaxDynamicSharedMemorySize, AT_HALVES * 2);

    k_f12v<<<BSZ * NN / 64, 512>>>(input, W, a);               // launch 1
    k_Zc<<<dim3(NN / 128, ZSPLIT, BSZ), 128>>>(adj);           // launch 2
    k_hgen<<<BSZ * NN / 64, 256, HG_FLOATS * 4>>>(input, W);   // launch 3
    k_att<<<dim3(NN / 128, BSZ), 512, AT_HALVES * 2>>>(out);   // launch 4 (profiled)
}